// round 1
// baseline (speedup 1.0000x reference)
#include <cuda_runtime.h>
#include <math_constants.h>

#define BATCH  4
#define SEQ    2048
#define DIM    1024
#define NHEADS 16
#define HDIM   64
#define MROWS  (BATCH*SEQ)   // 8192

// ---------------------------------------------------------------------------
// Scratch (no cudaMalloc allowed): Q, K, V, CTX each [8192, 1024] f32 = 32 MB
// ---------------------------------------------------------------------------
__device__ float g_Q[(size_t)MROWS * DIM];
__device__ float g_K[(size_t)MROWS * DIM];
__device__ float g_V[(size_t)MROWS * DIM];
__device__ float g_C[(size_t)MROWS * DIM];

// ---------------------------------------------------------------------------
// SGEMM: C[M,N] = A[M,K] @ B[K,N] (+ bias per column), 128x128x16 block tile,
// 256 threads, 8x8 per-thread micro-tile, float4 everywhere.
// Requires M%128==0, N%128==0, K%16==0 (true here: 8192/1024/1024).
// ---------------------------------------------------------------------------
template<bool BIAS>
__global__ __launch_bounds__(256, 2)
void sgemm128(const float* __restrict__ A, const float* __restrict__ B,
              const float* __restrict__ bias, float* __restrict__ C,
              int M, int N, int K)
{
    __shared__ float As[16][132];   // A tile transposed: As[k][m], +4 pad
    __shared__ float Bs[16][128];   // B tile: Bs[k][n]

    const int t  = threadIdx.x;
    const int tx = t & 15;
    const int ty = t >> 4;
    const int row0 = blockIdx.y << 7;
    const int col0 = blockIdx.x << 7;

    float acc[8][8];
#pragma unroll
    for (int i = 0; i < 8; i++)
#pragma unroll
        for (int j = 0; j < 8; j++) acc[i][j] = 0.f;

    const int la_r = t >> 2;          // 0..63
    const int la_c = (t & 3) << 2;    // 0,4,8,12
    const int lb_r = t >> 5;          // 0..7
    const int lb_c = (t & 31) << 2;   // 0..124

    for (int k0 = 0; k0 < K; k0 += 16) {
#pragma unroll
        for (int p = 0; p < 2; p++) {
            float4 a = *(const float4*)&A[(size_t)(row0 + la_r + p * 64) * K + k0 + la_c];
            As[la_c + 0][la_r + p * 64] = a.x;
            As[la_c + 1][la_r + p * 64] = a.y;
            As[la_c + 2][la_r + p * 64] = a.z;
            As[la_c + 3][la_r + p * 64] = a.w;
            *(float4*)&Bs[lb_r + p * 8][lb_c] =
                *(const float4*)&B[(size_t)(k0 + lb_r + p * 8) * N + col0 + lb_c];
        }
        __syncthreads();

#pragma unroll
        for (int k = 0; k < 16; k++) {
            float ar[8], br[8];
            *(float4*)&ar[0] = *(const float4*)&As[k][(ty << 2)];
            *(float4*)&ar[4] = *(const float4*)&As[k][64 + (ty << 2)];
            *(float4*)&br[0] = *(const float4*)&Bs[k][(tx << 2)];
            *(float4*)&br[4] = *(const float4*)&Bs[k][64 + (tx << 2)];
#pragma unroll
            for (int i = 0; i < 8; i++)
#pragma unroll
                for (int j = 0; j < 8; j++)
                    acc[i][j] = fmaf(ar[i], br[j], acc[i][j]);
        }
        __syncthreads();
    }

    float4 bv0 = make_float4(0.f, 0.f, 0.f, 0.f);
    float4 bv1 = make_float4(0.f, 0.f, 0.f, 0.f);
    if (BIAS) {
        bv0 = *(const float4*)&bias[col0 + (tx << 2)];
        bv1 = *(const float4*)&bias[col0 + 64 + (tx << 2)];
    }

#pragma unroll
    for (int i = 0; i < 8; i++) {
        int r = row0 + (ty << 2) + (i & 3) + ((i >> 2) << 6);
        float4 w0 = make_float4(acc[i][0] + bv0.x, acc[i][1] + bv0.y,
                                acc[i][2] + bv0.z, acc[i][3] + bv0.w);
        float4 w1 = make_float4(acc[i][4] + bv1.x, acc[i][5] + bv1.y,
                                acc[i][6] + bv1.z, acc[i][7] + bv1.w);
        *(float4*)&C[(size_t)r * N + col0 + (tx << 2)]      = w0;
        *(float4*)&C[(size_t)r * N + col0 + 64 + (tx << 2)] = w1;
    }
}

// ---------------------------------------------------------------------------
// Causal flash attention, fp32. One block per (q-tile of 64, head, batch).
// 256 threads: lane grid 16x16 (ty=row group, tx=col group), 4x4 per thread
// with STRIDED row/col assignment: row r_i = ty + 16*i, col c_j = tx + 16*j.
// Online softmax; Dh = 64.  Q pre-scaled by 1/sqrt(Dh).
// ---------------------------------------------------------------------------
#define LDT 68                       // padded row stride (mult of 4 for float4)
#define ATT_SMEM (4 * 64 * LDT * 4)  // Qs, Ks, Vs, Ps -> 69632 bytes

__global__ __launch_bounds__(256)
void attn64(const float* __restrict__ Q, const float* __restrict__ K,
            const float* __restrict__ V, float* __restrict__ O)
{
    extern __shared__ float sm[];
    float* Qs = sm;
    float* Ks = Qs + 64 * LDT;
    float* Vs = Ks + 64 * LDT;
    float* Ps = Vs + 64 * LDT;

    const int qt = blockIdx.x;
    const int h  = blockIdx.y;
    const int b  = blockIdx.z;
    const int t  = threadIdx.x;
    const int tx = t & 15;
    const int ty = t >> 4;
    const int q0 = qt << 6;

    const float* Qb = Q + ((size_t)b * SEQ + q0) * DIM + h * HDIM;
    const float* Kb = K + (size_t)b * SEQ * DIM + h * HDIM;
    const float* Vb = V + (size_t)b * SEQ * DIM + h * HDIM;

    // Load Q tile (64 x 64), fold in softmax scale 1/sqrt(64) = 0.125
    for (int i = t; i < 1024; i += 256) {
        int rr = i >> 4, cc = (i & 15) << 2;
        float4 v4 = *(const float4*)&Qb[(size_t)rr * DIM + cc];
        float* dst = &Qs[rr * LDT + cc];
        dst[0] = v4.x * 0.125f; dst[1] = v4.y * 0.125f;
        dst[2] = v4.z * 0.125f; dst[3] = v4.w * 0.125f;
    }

    float m_i[4], l_i[4], o[4][4];
#pragma unroll
    for (int i = 0; i < 4; i++) {
        m_i[i] = -CUDART_INF_F;
        l_i[i] = 0.f;
#pragma unroll
        for (int dd = 0; dd < 4; dd++) o[i][dd] = 0.f;
    }

    for (int kt = 0; kt <= qt; kt++) {
        __syncthreads();  // previous iteration's Ks/Vs/Ps fully consumed

        const float* Kt = Kb + ((size_t)(kt << 6)) * DIM;
        const float* Vt = Vb + ((size_t)(kt << 6)) * DIM;
        for (int i = t; i < 1024; i += 256) {
            int rr = i >> 4, cc = (i & 15) << 2;
            float4 kv = *(const float4*)&Kt[(size_t)rr * DIM + cc];
            float* kd = &Ks[rr * LDT + cc];
            kd[0] = kv.x; kd[1] = kv.y; kd[2] = kv.z; kd[3] = kv.w;
            float4 vv = *(const float4*)&Vt[(size_t)rr * DIM + cc];
            float* vd = &Vs[rr * LDT + cc];
            vd[0] = vv.x; vd[1] = vv.y; vd[2] = vv.z; vd[3] = vv.w;
        }
        __syncthreads();

        // ---- Phase 1: S = Q K^T (4x4 per thread, vectorized over d) ----
        float s[4][4];
#pragma unroll
        for (int i = 0; i < 4; i++)
#pragma unroll
            for (int j = 0; j < 4; j++) s[i][j] = 0.f;

#pragma unroll
        for (int d4 = 0; d4 < 16; d4++) {
            float4 q4[4], k4[4];
#pragma unroll
            for (int i = 0; i < 4; i++)
                q4[i] = *(const float4*)&Qs[(ty + (i << 4)) * LDT + (d4 << 2)];
#pragma unroll
            for (int j = 0; j < 4; j++)
                k4[j] = *(const float4*)&Ks[(tx + (j << 4)) * LDT + (d4 << 2)];
#pragma unroll
            for (int i = 0; i < 4; i++)
#pragma unroll
                for (int j = 0; j < 4; j++) {
                    s[i][j] = fmaf(q4[i].x, k4[j].x, s[i][j]);
                    s[i][j] = fmaf(q4[i].y, k4[j].y, s[i][j]);
                    s[i][j] = fmaf(q4[i].z, k4[j].z, s[i][j]);
                    s[i][j] = fmaf(q4[i].w, k4[j].w, s[i][j]);
                }
        }

        // Causal mask (only the diagonal tile needs it)
        if (kt == qt) {
#pragma unroll
            for (int i = 0; i < 4; i++)
#pragma unroll
                for (int j = 0; j < 4; j++)
                    if (tx + (j << 4) > ty + (i << 4)) s[i][j] = -CUDART_INF_F;
        }

        // ---- Online softmax update (rows reduced across the 16 tx lanes) ----
#pragma unroll
        for (int i = 0; i < 4; i++) {
            float rm = fmaxf(fmaxf(s[i][0], s[i][1]), fmaxf(s[i][2], s[i][3]));
            rm = fmaxf(rm, __shfl_xor_sync(0xffffffffu, rm, 1));
            rm = fmaxf(rm, __shfl_xor_sync(0xffffffffu, rm, 2));
            rm = fmaxf(rm, __shfl_xor_sync(0xffffffffu, rm, 4));
            rm = fmaxf(rm, __shfl_xor_sync(0xffffffffu, rm, 8));
            float mnew = fmaxf(m_i[i], rm);
            float al   = __expf(m_i[i] - mnew);
            m_i[i] = mnew;

            float ps = 0.f;
#pragma unroll
            for (int j = 0; j < 4; j++) {
                float p = __expf(s[i][j] - mnew);
                s[i][j] = p;
                ps += p;
            }
            ps += __shfl_xor_sync(0xffffffffu, ps, 1);
            ps += __shfl_xor_sync(0xffffffffu, ps, 2);
            ps += __shfl_xor_sync(0xffffffffu, ps, 4);
            ps += __shfl_xor_sync(0xffffffffu, ps, 8);

            l_i[i] = l_i[i] * al + ps;
#pragma unroll
            for (int dd = 0; dd < 4; dd++) o[i][dd] *= al;

#pragma unroll
            for (int j = 0; j < 4; j++)
                Ps[(ty + (i << 4)) * LDT + tx + (j << 4)] = s[i][j];
        }
        __syncthreads();

        // ---- Phase 2: O += P V  (thread owns rows ty+16i, dims tx+16dd) ----
#pragma unroll 4
        for (int j = 0; j < 64; j++) {
            float pv[4], vv[4];
#pragma unroll
            for (int i = 0; i < 4; i++)
                pv[i] = Ps[(ty + (i << 4)) * LDT + j];
#pragma unroll
            for (int dd = 0; dd < 4; dd++)
                vv[dd] = Vs[j * LDT + tx + (dd << 4)];
#pragma unroll
            for (int i = 0; i < 4; i++)
#pragma unroll
                for (int dd = 0; dd < 4; dd++)
                    o[i][dd] = fmaf(pv[i], vv[dd], o[i][dd]);
        }
    }

    // ---- Final normalize + write ctx in [B, S, H*Dh] layout ----
    float* Ob = O + ((size_t)b * SEQ + q0) * DIM + h * HDIM;
#pragma unroll
    for (int i = 0; i < 4; i++) {
        float inv = 1.0f / l_i[i];
#pragma unroll
        for (int dd = 0; dd < 4; dd++)
            Ob[(size_t)(ty + (i << 4)) * DIM + tx + (dd << 4)] = o[i][dd] * inv;
    }
}

// ---------------------------------------------------------------------------
// Launch
// ---------------------------------------------------------------------------
extern "C" void kernel_launch(void* const* d_in, const int* in_sizes, int n_in,
                              void* d_out, int out_size)
{
    const float* x  = (const float*)d_in[0];
    const float* Wq = (const float*)d_in[1];
    const float* Wk = (const float*)d_in[2];
    const float* Wv = (const float*)d_in[3];
    const float* Wo = (const float*)d_in[4];
    const float* bo = (const float*)d_in[5];
    float* out = (float*)d_out;

    float *qp, *kp, *vp, *cp;
    cudaGetSymbolAddress((void**)&qp, g_Q);
    cudaGetSymbolAddress((void**)&kp, g_K);
    cudaGetSymbolAddress((void**)&vp, g_V);
    cudaGetSymbolAddress((void**)&cp, g_C);

    cudaFuncSetAttribute(attn64, cudaFuncAttributeMaxDynamicSharedMemorySize, ATT_SMEM);

    dim3 gg(DIM / 128, MROWS / 128);  // (8, 64)
    sgemm128<false><<<gg, 256>>>(x, Wq, nullptr, qp, MROWS, DIM, DIM);
    sgemm128<false><<<gg, 256>>>(x, Wk, nullptr, kp, MROWS, DIM, DIM);
    sgemm128<false><<<gg, 256>>>(x, Wv, nullptr, vp, MROWS, DIM, DIM);

    dim3 ga(SEQ / 64, NHEADS, BATCH); // (32, 16, 4)
    attn64<<<ga, 256, ATT_SMEM>>>(qp, kp, vp, cp);

    sgemm128<true><<<gg, 256>>>(cp, Wo, bo, out, MROWS, DIM, DIM);
}

// round 2
// speedup vs baseline: 2.9639x; 2.9639x over previous
#include <cuda_runtime.h>
#include <math_constants.h>

#define BATCH  4
#define SEQ    2048
#define DIM    1024
#define NHEADS 16
#define HDIM   64
#define MROWS  (BATCH*SEQ)   // 8192

// ---------------------------------------------------------------------------
// Scratch (no cudaMalloc allowed): Q, K, V, CTX each [8192, 1024] f32 = 32 MB
// ---------------------------------------------------------------------------
__device__ float g_Q[(size_t)MROWS * DIM];
__device__ float g_K[(size_t)MROWS * DIM];
__device__ float g_V[(size_t)MROWS * DIM];
__device__ float g_C[(size_t)MROWS * DIM];

// ---------------------------------------------------------------------------
// tf32 helpers
// ---------------------------------------------------------------------------
__device__ __forceinline__ unsigned f2tf(float x) {
    unsigned r;
    asm("cvt.rna.tf32.f32 %0, %1;" : "=r"(r) : "f"(x));
    return r;
}
__device__ __forceinline__ float tf32r(float x) { return __uint_as_float(f2tf(x)); }
__device__ __forceinline__ unsigned fu(float x)  { return __float_as_uint(x); }

// mma.sync m16n8k8 tf32, fp32 accumulate
__device__ __forceinline__ void mma8(float c[4], const unsigned a[4], const unsigned b[2]) {
    asm volatile(
        "mma.sync.aligned.m16n8k8.row.col.f32.tf32.tf32.f32 "
        "{%0,%1,%2,%3}, {%4,%5,%6,%7}, {%8,%9}, {%0,%1,%2,%3};\n"
        : "+f"(c[0]), "+f"(c[1]), "+f"(c[2]), "+f"(c[3])
        : "r"(a[0]), "r"(a[1]), "r"(a[2]), "r"(a[3]), "r"(b[0]), "r"(b[1]));
}

// ---------------------------------------------------------------------------
// Tensor-core GEMM: C[M,N] = A[M,K] @ B[K,N] (+bias). Block 128x128, K-step 32,
// 8 warps (warp tile 32x64). As[m][k] stride 36, Bs[k][n] stride 136 — both
// fragment-load conflict-free. tf32 conversion at staging.
// ---------------------------------------------------------------------------
template<bool BIAS>
__global__ __launch_bounds__(256, 2)
void gemm_tc(const float* __restrict__ A, const float* __restrict__ B,
             const float* __restrict__ bias, float* __restrict__ C,
             int M, int N, int K)
{
    __shared__ float As[128][36];
    __shared__ float Bs[32][136];

    const int t    = threadIdx.x;
    const int warp = t >> 5, lane = t & 31;
    const int lr   = lane >> 2, lc = lane & 3;
    const int wm   = (warp >> 1) << 5;   // 0,32,64,96
    const int wn   = (warp & 1) << 6;    // 0,64
    const int row0 = blockIdx.y << 7, col0 = blockIdx.x << 7;

    float acc[2][8][4];
#pragma unroll
    for (int mt = 0; mt < 2; mt++)
#pragma unroll
        for (int nt = 0; nt < 8; nt++)
#pragma unroll
            for (int i = 0; i < 4; i++) acc[mt][nt][i] = 0.f;

    const int ar = t >> 3;          // 0..31
    const int ac = (t & 7) << 2;    // 0..28
    const int bk = t >> 5;          // 0..7
    const int bn = (t & 31) << 2;   // 0..124

    const float* Ag = A + (size_t)(row0 + ar) * K + ac;
    const float* Bg = B + (size_t)bk * N + col0 + bn;

    for (int k0 = 0; k0 < K; k0 += 32) {
        float4 av[4], bv[4];
#pragma unroll
        for (int p = 0; p < 4; p++) {
            av[p] = *(const float4*)&Ag[(size_t)(p << 5) * K + k0];
            bv[p] = *(const float4*)&Bg[(size_t)((p << 3) + k0) * N];
        }
        __syncthreads();
#pragma unroll
        for (int p = 0; p < 4; p++) {
            *(float4*)&As[ar + (p << 5)][ac] =
                make_float4(tf32r(av[p].x), tf32r(av[p].y), tf32r(av[p].z), tf32r(av[p].w));
            *(float4*)&Bs[bk + (p << 3)][bn] =
                make_float4(tf32r(bv[p].x), tf32r(bv[p].y), tf32r(bv[p].z), tf32r(bv[p].w));
        }
        __syncthreads();

#pragma unroll
        for (int s = 0; s < 4; s++) {
            const int kk = (s << 3) + lc;
            unsigned af[2][4], bf[8][2];
#pragma unroll
            for (int mt = 0; mt < 2; mt++) {
                int m0 = wm + (mt << 4) + lr;
                af[mt][0] = fu(As[m0][kk]);
                af[mt][1] = fu(As[m0 + 8][kk]);
                af[mt][2] = fu(As[m0][kk + 4]);
                af[mt][3] = fu(As[m0 + 8][kk + 4]);
            }
#pragma unroll
            for (int nt = 0; nt < 8; nt++) {
                int n0 = wn + (nt << 3) + lr;
                bf[nt][0] = fu(Bs[kk][n0]);
                bf[nt][1] = fu(Bs[kk + 4][n0]);
            }
#pragma unroll
            for (int mt = 0; mt < 2; mt++)
#pragma unroll
                for (int nt = 0; nt < 8; nt++)
                    mma8(acc[mt][nt], af[mt], bf[nt]);
        }
    }

#pragma unroll
    for (int nt = 0; nt < 8; nt++) {
        int c = col0 + wn + (nt << 3) + (lc << 1);
        float bx = 0.f, by = 0.f;
        if (BIAS) { bx = bias[c]; by = bias[c + 1]; }
#pragma unroll
        for (int mt = 0; mt < 2; mt++) {
            int r = row0 + wm + (mt << 4) + lr;
            *(float2*)&C[(size_t)r * N + c] =
                make_float2(acc[mt][nt][0] + bx, acc[mt][nt][1] + by);
            *(float2*)&C[(size_t)(r + 8) * N + c] =
                make_float2(acc[mt][nt][2] + bx, acc[mt][nt][3] + by);
        }
    }
}

// ---------------------------------------------------------------------------
// Tensor-core causal flash attention. Block = 64 q-rows x (head, batch);
// 4 warps, 16 q-rows each. Q lives in A-fragments (regs). Per kv-tile (64):
// S = Q K^T via 64 mma, online softmax on C-fragments, P -> smem (tf32),
// O += P V via 64 mma. Ks stride 68, Vs stride 72, Ps stride 68.
// ---------------------------------------------------------------------------
#define LK 68
#define LV 72
#define LP 68
#define ATT_SMEM ((64*LK + 64*LV + 64*LP) * 4)   // 53248 bytes

__global__ __launch_bounds__(128)
void attn_tc(const float* __restrict__ Q, const float* __restrict__ K,
             const float* __restrict__ V, float* __restrict__ O)
{
    extern __shared__ float sm[];
    float* Ks = sm;
    float* Vs = Ks + 64 * LK;
    float* Ps = Vs + 64 * LV;

    const int qt = blockIdx.x, h = blockIdx.y, b = blockIdx.z;
    const int t    = threadIdx.x;
    const int warp = t >> 5, lane = t & 31;
    const int lr   = lane >> 2, lc = lane & 3;
    const int q0   = qt << 6, w16 = warp << 4;

    const float* Qb = Q + ((size_t)(b * SEQ + q0 + w16)) * DIM + h * HDIM;

    // Stage this warp's 16x64 Q (scaled by 1/sqrt(64)) into Ps, then to frags
#pragma unroll
    for (int j = 0; j < 8; j++) {
        int f = lane + (j << 5);
        int r = f >> 4, c4 = (f & 15) << 2;
        float4 v = *(const float4*)&Qb[(size_t)r * DIM + c4];
        *(float4*)&Ps[(w16 + r) * LP + c4] =
            make_float4(tf32r(v.x * 0.125f), tf32r(v.y * 0.125f),
                        tf32r(v.z * 0.125f), tf32r(v.w * 0.125f));
    }
    __syncwarp();

    unsigned qa[8][4];
#pragma unroll
    for (int s = 0; s < 8; s++) {
        int kk = (s << 3) + lc;
        qa[s][0] = fu(Ps[(w16 + lr) * LP + kk]);
        qa[s][1] = fu(Ps[(w16 + lr + 8) * LP + kk]);
        qa[s][2] = fu(Ps[(w16 + lr) * LP + kk + 4]);
        qa[s][3] = fu(Ps[(w16 + lr + 8) * LP + kk + 4]);
    }

    float o[8][4];
#pragma unroll
    for (int nt = 0; nt < 8; nt++)
#pragma unroll
        for (int i = 0; i < 4; i++) o[nt][i] = 0.f;
    float mrow[2] = {-CUDART_INF_F, -CUDART_INF_F};
    float lsum[2] = {0.f, 0.f};

    const float* Kb = K + (size_t)b * SEQ * DIM + h * HDIM;
    const float* Vb = V + (size_t)b * SEQ * DIM + h * HDIM;

    for (int kt = 0; kt <= qt; kt++) {
        __syncthreads();
        const float* Kt = Kb + ((size_t)(kt << 6)) * DIM;
        const float* Vt = Vb + ((size_t)(kt << 6)) * DIM;
#pragma unroll
        for (int j = 0; j < 8; j++) {
            int f = t + (j << 7);
            int r = f >> 4, c4 = (f & 15) << 2;
            float4 kv = *(const float4*)&Kt[(size_t)r * DIM + c4];
            float4 vv = *(const float4*)&Vt[(size_t)r * DIM + c4];
            *(float4*)&Ks[r * LK + c4] =
                make_float4(tf32r(kv.x), tf32r(kv.y), tf32r(kv.z), tf32r(kv.w));
            *(float4*)&Vs[r * LV + c4] =
                make_float4(tf32r(vv.x), tf32r(vv.y), tf32r(vv.z), tf32r(vv.w));
        }
        __syncthreads();

        // ---- S = Q K^T ----
        float sc[8][4];
#pragma unroll
        for (int nt = 0; nt < 8; nt++)
#pragma unroll
            for (int i = 0; i < 4; i++) sc[nt][i] = 0.f;

#pragma unroll
        for (int s = 0; s < 8; s++) {
            int kk = (s << 3) + lc;
#pragma unroll
            for (int nt = 0; nt < 8; nt++) {
                unsigned bf[2];
                bf[0] = fu(Ks[((nt << 3) + lr) * LK + kk]);
                bf[1] = fu(Ks[((nt << 3) + lr) * LK + kk + 4]);
                mma8(sc[nt], qa[s], bf);
            }
        }

        // ---- causal mask (diagonal tile only) ----
        if (kt == qt) {
#pragma unroll
            for (int nt = 0; nt < 8; nt++)
#pragma unroll
                for (int i = 0; i < 4; i++) {
                    int rr = w16 + lr + ((i >> 1) << 3);
                    int cc = (nt << 3) + (lc << 1) + (i & 1);
                    if (cc > rr) sc[nt][i] = -CUDART_INF_F;
                }
        }

        // ---- online softmax (rows owned by quads; shfl xor 1,2) ----
#pragma unroll
        for (int hh = 0; hh < 2; hh++) {
            const int i0 = hh << 1;
            float rm = -CUDART_INF_F;
#pragma unroll
            for (int nt = 0; nt < 8; nt++)
                rm = fmaxf(rm, fmaxf(sc[nt][i0], sc[nt][i0 + 1]));
            rm = fmaxf(rm, __shfl_xor_sync(0xffffffffu, rm, 1));
            rm = fmaxf(rm, __shfl_xor_sync(0xffffffffu, rm, 2));
            float mnew  = fmaxf(mrow[hh], rm);
            float alpha = __expf(mrow[hh] - mnew);
            mrow[hh] = mnew;
            float ps = 0.f;
#pragma unroll
            for (int nt = 0; nt < 8; nt++) {
                float p0 = __expf(sc[nt][i0]     - mnew);
                float p1 = __expf(sc[nt][i0 + 1] - mnew);
                sc[nt][i0] = p0; sc[nt][i0 + 1] = p1;
                ps += p0 + p1;
            }
            ps += __shfl_xor_sync(0xffffffffu, ps, 1);
            ps += __shfl_xor_sync(0xffffffffu, ps, 2);
            lsum[hh] = lsum[hh] * alpha + ps;
#pragma unroll
            for (int nt = 0; nt < 8; nt++) {
                o[nt][i0]     *= alpha;
                o[nt][i0 + 1] *= alpha;
            }
            const int rbase = (w16 + lr + (hh << 3)) * LP;
#pragma unroll
            for (int nt = 0; nt < 8; nt++) {
                Ps[rbase + (nt << 3) + (lc << 1)]     = tf32r(sc[nt][i0]);
                Ps[rbase + (nt << 3) + (lc << 1) + 1] = tf32r(sc[nt][i0 + 1]);
            }
        }
        __syncwarp();

        // ---- O += P V ----
#pragma unroll
        for (int s = 0; s < 8; s++) {
            int kk = (s << 3) + lc;
            unsigned pa[4];
            pa[0] = fu(Ps[(w16 + lr) * LP + kk]);
            pa[1] = fu(Ps[(w16 + lr + 8) * LP + kk]);
            pa[2] = fu(Ps[(w16 + lr) * LP + kk + 4]);
            pa[3] = fu(Ps[(w16 + lr + 8) * LP + kk + 4]);
#pragma unroll
            for (int nt = 0; nt < 8; nt++) {
                unsigned bf[2];
                bf[0] = fu(Vs[kk * LV + (nt << 3) + lr]);
                bf[1] = fu(Vs[(kk + 4) * LV + (nt << 3) + lr]);
                mma8(o[nt], pa, bf);
            }
        }
    }

    // ---- normalize + write ----
    float* Ob = O + ((size_t)(b * SEQ + q0 + w16)) * DIM + h * HDIM;
#pragma unroll
    for (int hh = 0; hh < 2; hh++) {
        float inv = 1.0f / lsum[hh];
        int r = lr + (hh << 3);
#pragma unroll
        for (int nt = 0; nt < 8; nt++) {
            float2 w = make_float2(o[nt][(hh << 1)] * inv, o[nt][(hh << 1) + 1] * inv);
            *(float2*)&Ob[(size_t)r * DIM + (nt << 3) + (lc << 1)] = w;
        }
    }
}

// ---------------------------------------------------------------------------
// Launch
// ---------------------------------------------------------------------------
extern "C" void kernel_launch(void* const* d_in, const int* in_sizes, int n_in,
                              void* d_out, int out_size)
{
    const float* x  = (const float*)d_in[0];
    const float* Wq = (const float*)d_in[1];
    const float* Wk = (const float*)d_in[2];
    const float* Wv = (const float*)d_in[3];
    const float* Wo = (const float*)d_in[4];
    const float* bo = (const float*)d_in[5];
    float* out = (float*)d_out;

    float *qp, *kp, *vp, *cp;
    cudaGetSymbolAddress((void**)&qp, g_Q);
    cudaGetSymbolAddress((void**)&kp, g_K);
    cudaGetSymbolAddress((void**)&vp, g_V);
    cudaGetSymbolAddress((void**)&cp, g_C);

    cudaFuncSetAttribute(attn_tc, cudaFuncAttributeMaxDynamicSharedMemorySize, ATT_SMEM);

    dim3 gg(DIM / 128, MROWS / 128);  // (8, 64)
    gemm_tc<false><<<gg, 256>>>(x, Wq, nullptr, qp, MROWS, DIM, DIM);
    gemm_tc<false><<<gg, 256>>>(x, Wk, nullptr, kp, MROWS, DIM, DIM);
    gemm_tc<false><<<gg, 256>>>(x, Wv, nullptr, vp, MROWS, DIM, DIM);

    dim3 ga(SEQ / 64, NHEADS, BATCH); // (32, 16, 4)
    attn_tc<<<ga, 128, ATT_SMEM>>>(qp, kp, vp, cp);

    gemm_tc<true><<<gg, 256>>>(cp, Wo, bo, out, MROWS, DIM, DIM);
}